// round 6
// baseline (speedup 1.0000x reference)
#include <cuda_runtime.h>
#include <cuda_bf16.h>
#include <math.h>

// Problem constants
#define BB 4
#define CC 32
#define WW 256
#define HH 256
#define KK 9
#define OC_OFF 10
#define PIX (WW*HH)

// k_main tile: 32 w-rows x 32 h-cols, 256 threads, 4 px/thread
#define TWM 32
#define THM 32
#define RROWS 42           // TWM + 10
#define CCOLS 42           // THM + 10
#define NCI 8              // ci per chunk
#define XCH (NCI*RROWS*CCOLS)   // 14112 floats per chunk
#define WSZ (KK*CC*CC)          // 9216

typedef unsigned long long u64;

__device__ __forceinline__ u64 ffma2(u64 a, u64 b, u64 c) {
    u64 d;
    asm("fma.rn.f32x2 %0, %1, %2, %3;" : "=l"(d) : "l"(a), "l"(b), "l"(c));
    return d;
}
__device__ __forceinline__ u64 pack2(float v) {
    u64 d; unsigned u = __float_as_uint(v);
    asm("mov.b64 %0, {%1, %1};" : "=l"(d) : "r"(u));
    return d;
}
__device__ __forceinline__ void unpack2(u64 in, float& lo, float& hi) {
    unsigned a, b;
    asm("mov.b64 {%0, %1}, %2;" : "=r"(a), "=r"(b) : "l"(in));
    lo = __uint_as_float(a); hi = __uint_as_float(b);
}

// Scratch
__device__ float g_off[BB*OC_OFF*PIX];
__device__ float g_py [BB*KK*PIX];
__device__ float g_pre[BB*CC*PIX];
__device__ float g_soff[BB*5*2];
__device__ float g_mroff[BB*5*2];
__device__ float g_sout[BB*8*2];
__device__ float g_mrout[BB*8*2];

// ---------------------------------------------------------------- zero stats
__global__ void k_zero() {
    int t = threadIdx.x;
    if (t < BB*5*2) g_soff[t] = 0.f;
    if (t < BB*8*2) g_sout[t] = 0.f;
}

// ---------------------- K1: 3x3 conv, 32 -> 10 ch, 4 pixels (w-rows) / thread
__global__ void __launch_bounds__(256, 2)
k_conv_off(const float* __restrict__ x,
           const float* __restrict__ w_off,
           const float* __restrict__ b_off) {
    __shared__ __align__(8) float ws[CC*9*OC_OFF];   // [ci][tap][10]
    __shared__ float s_sum[5], s_sq[5];
    int b   = blockIdx.y;
    int wb  = blockIdx.x * 4;
    int tid = threadIdx.x;
    int h   = tid;

    for (int i = tid; i < CC*9*OC_OFF; i += 256) {
        int o = i % OC_OFF; int rest = i / OC_OFF;
        int tap = rest % 9; int ci = rest / 9;
        int dy = tap / 3, dx = tap % 3;
        ws[i] = w_off[((o*CC + ci)*3 + dy)*3 + dx];
    }
    if (tid < 5) { s_sum[tid] = 0.f; s_sq[tid] = 0.f; }
    __syncthreads();

    u64 acc[4][5];
    const u64* b2 = (const u64*)b_off;
#pragma unroll
    for (int p = 0; p < 4; p++)
#pragma unroll
        for (int j = 0; j < 5; j++) acc[p][j] = b2[j];

    const float* xb = x + b*CC*PIX;
#pragma unroll 1
    for (int ci = 0; ci < CC; ci++) {
        const float* xc = xb + ci*PIX;
        u64 v2[6][3];
#pragma unroll
        for (int rr = 0; rr < 6; rr++) {
            int r = wb - 1 + rr;
            bool rok = (unsigned)r < 256u;
#pragma unroll
            for (int dx = 0; dx < 3; dx++) {
                int c = h + dx - 1;
                float v = (rok && (unsigned)c < 256u) ? xc[r*256 + c] : 0.f;
                v2[rr][dx] = pack2(v);
            }
        }
#pragma unroll
        for (int tap = 0; tap < 9; tap++) {
            int dy = tap / 3, dx = tap % 3;
            const u64* wp = (const u64*)&ws[(ci*9 + tap)*OC_OFF];
            u64 w0 = wp[0], w1 = wp[1], w2 = wp[2], w3 = wp[3], w4 = wp[4];
#pragma unroll
            for (int p = 0; p < 4; p++) {
                u64 vv = v2[dy + p][dx];
                acc[p][0] = ffma2(vv, w0, acc[p][0]);
                acc[p][1] = ffma2(vv, w1, acc[p][1]);
                acc[p][2] = ffma2(vv, w2, acc[p][2]);
                acc[p][3] = ffma2(vv, w3, acc[p][3]);
                acc[p][4] = ffma2(vv, w4, acc[p][4]);
            }
        }
    }

    float s[5], q[5];
#pragma unroll
    for (int j = 0; j < 5; j++) { s[j] = 0.f; q[j] = 0.f; }
#pragma unroll
    for (int p = 0; p < 4; p++) {
        int w = wb + p;
        float* outp = g_off + b*OC_OFF*PIX + w*256 + h;
#pragma unroll
        for (int j = 0; j < 5; j++) {
            float v0, v1; unpack2(acc[p][j], v0, v1);
            outp[(2*j)*PIX]   = v0;
            outp[(2*j+1)*PIX] = v1;
            s[j] += v0 + v1;
            q[j] += v0*v0 + v1*v1;
        }
    }
#pragma unroll
    for (int j = 0; j < 5; j++) {
        float ss = s[j], qq = q[j];
#pragma unroll
        for (int off = 16; off; off >>= 1) {
            ss += __shfl_xor_sync(0xffffffffu, ss, off);
            qq += __shfl_xor_sync(0xffffffffu, qq, off);
        }
        if ((tid & 31) == 0) { atomicAdd(&s_sum[j], ss); atomicAdd(&s_sq[j], qq); }
    }
    __syncthreads();
    if (tid < 5) {
        atomicAdd(&g_soff[(b*5 + tid)*2 + 0], s_sum[tid]);
        atomicAdd(&g_soff[(b*5 + tid)*2 + 1], s_sq[tid]);
    }
}

// --------------------------------------------- K2a: finalize offset GN stats
__global__ void k_stats_off() {
    int t = threadIdx.x;
    if (t < BB*5) {
        float S = g_soff[t*2], Q = g_soff[t*2 + 1];
        float inv = 1.f / (2.f * (float)PIX);
        float mu  = S * inv;
        float var = Q * inv - mu*mu;
        g_mroff[t*2]     = mu;
        g_mroff[t*2 + 1] = rsqrtf(var + 1e-5f);
    }
}

// --------------------- K3: GN + tanh + cumsum -> sampling coordinate field py
__global__ void k_py(const float* __restrict__ sc, const float* __restrict__ bi) {
    int b = blockIdx.y;
    int p = blockIdx.x*256 + threadIdx.x;
    int w = p >> 8;

    float t[9];
#pragma unroll
    for (int c = 0; c < 9; c++) {
        float v  = g_off[(b*OC_OFF + c)*PIX + p];
        int   g  = c >> 1;
        float mu = g_mroff[(b*5 + g)*2], rs = g_mroff[(b*5 + g)*2 + 1];
        t[c] = tanhf(fmaf((v - mu)*rs, sc[c], bi[c]));
    }
    float yc[9];
    float r0 = t[3];
    float r1 = r0 + t[2];
    float r2 = r1 + t[1];
    float r3 = r2 + t[0];
    yc[0] = r3; yc[1] = r2; yc[2] = r1; yc[3] = r0;
    yc[4] = 0.f;
    float u0 = t[5];
    float u1 = u0 + t[6];
    float u2 = u1 + t[7];
    float u3 = u2 + t[8];
    yc[5] = u0; yc[6] = u1; yc[7] = u2; yc[8] = u3;

#pragma unroll
    for (int k = 0; k < 9; k++) {
        float y  = (float)w + yc[k];
        float tt = fminf(fmaxf(y * (1.f/256.f), 0.f), 1.f);
        g_py[(b*KK + k)*PIX + p] = tt * 255.f;
    }
}

// ------------- K4: fused bilinear-sample + (K,1)-strided conv, 4 px / thread
__global__ void __launch_bounds__(256, 1)
k_main(const float* __restrict__ x,
       const float* __restrict__ wdsc,
       const float* __restrict__ bdsc) {
    extern __shared__ __align__(16) float sm[];
    float* Xs  = sm;                  // XCH (one ci-chunk)
    float* Ws  = Xs + XCH;            // WSZ [k][ci][co]
    float* sOs = Ws + WSZ;            // 8
    float* sOq = sOs + 8;             // 8

    int b  = blockIdx.z;
    int w0 = blockIdx.y * TWM;
    int h0 = blockIdx.x * THM;
    int tid = threadIdx.x;
    int rbase = w0 - 5, cbase = h0 - 5;

    int hl = tid & 31, wl = tid >> 5;      // wl in 0..7
    int h = h0 + hl;
    int wP[4];
#pragma unroll
    for (int p = 0; p < 4; p++) wP[p] = w0 + wl + 8*p;

    // weights: [k][ci][co], co contiguous
    for (int i = tid; i < WSZ; i += 256) {
        int co = i & 31; int rest = i >> 5;
        int ci = rest & 31; int k = rest >> 5;
        Ws[i] = wdsc[(co*CC + ci)*KK + k];
    }
    if (tid < 8) { sOs[tid] = 0.f; sOq[tid] = 0.f; }

    u64 acc[4][16];
#pragma unroll
    for (int p = 0; p < 4; p++)
#pragma unroll
        for (int i = 0; i < 16; i++) acc[p][i] = 0ull;

    const float* xb = x + b*CC*PIX;
    const float* pyb = g_py + b*KK*PIX;

#pragma unroll 1
    for (int chunk = 0; chunk < 4; chunk++) {
        __syncthreads();
        // load 8-channel X chunk with clamped halo
        for (int i = tid; i < XCH; i += 256) {
            int c = i % CCOLS; int rest = i / CCOLS;
            int r = rest % RROWS; int ci8 = rest / RROWS;
            int gr = min(max(rbase + r, 0), 255);
            int gc = min(max(cbase + c, 0), 255);
            Xs[i] = xb[(chunk*NCI + ci8)*PIX + gr*256 + gc];
        }
        __syncthreads();

#pragma unroll 1
        for (int k = 0; k < KK; k++) {
            // column geometry (shared by all 4 pixels: same h)
            float fx  = (float)(h + k - 4);
            float px  = fminf(fmaxf(fx * (1.f/256.f), 0.f), 1.f) * 255.f;
            float x0f = floorf(px);
            float wx  = px - x0f;
            int x0i = (int)x0f;
            int x1i = min(x0i + 1, 255);
            int cs0 = x0i - cbase, cs1 = x1i - cbase;

            // row geometry per pixel
            int o0[4], o1[4], o2[4], o3[4];
            float tw0[4], tw1[4], tw2[4], tw3[4];
#pragma unroll
            for (int p = 0; p < 4; p++) {
                float py = __ldg(&pyb[k*PIX + wP[p]*256 + h]);
                float y0 = floorf(py);
                float wy = py - y0;
                int y0i = (int)y0;
                int y1i = min(y0i + 1, 255);
                int rs0 = y0i - rbase, rs1 = y1i - rbase;
                tw0[p] = (1.f - wy)*(1.f - wx);
                tw1[p] = (1.f - wy)*wx;
                tw2[p] = wy*(1.f - wx);
                tw3[p] = wy*wx;
                o0[p] = rs0*CCOLS + cs0;
                o1[p] = rs0*CCOLS + cs1;
                o2[p] = rs1*CCOLS + cs0;
                o3[p] = rs1*CCOLS + cs1;
            }

            const float* WkBase = Ws + (k*CC + chunk*NCI)*CC;
#pragma unroll
            for (int ci8 = 0; ci8 < NCI; ci8++) {
                const float* Xc = Xs + ci8*(RROWS*CCOLS);
                u64 v2[4];
#pragma unroll
                for (int p = 0; p < 4; p++) {
                    float v = tw0[p]*Xc[o0[p]];
                    v = fmaf(tw1[p], Xc[o1[p]], v);
                    v = fmaf(tw2[p], Xc[o2[p]], v);
                    v = fmaf(tw3[p], Xc[o3[p]], v);
                    v2[p] = pack2(v);
                }
                const u64* wp = (const u64*)(WkBase + ci8*CC);
#pragma unroll
                for (int j = 0; j < 16; j++) {
                    u64 wv = wp[j];
                    acc[0][j] = ffma2(v2[0], wv, acc[0][j]);
                    acc[1][j] = ffma2(v2[1], wv, acc[1][j]);
                    acc[2][j] = ffma2(v2[2], wv, acc[2][j]);
                    acc[3][j] = ffma2(v2[3], wv, acc[3][j]);
                }
            }
        }
    }

    // store pre-GN output + accumulate GN stats (per 4-channel group)
    float s[8], q[8];
#pragma unroll
    for (int g = 0; g < 8; g++) { s[g] = 0.f; q[g] = 0.f; }
#pragma unroll
    for (int p = 0; p < 4; p++) {
        float* outp = g_pre + (b*CC)*PIX + wP[p]*256 + h;
#pragma unroll
        for (int j = 0; j < 16; j++) {
            float v0, v1; unpack2(acc[p][j], v0, v1);
            v0 += __ldg(&bdsc[2*j]);
            v1 += __ldg(&bdsc[2*j+1]);
            outp[(2*j)*PIX]   = v0;
            outp[(2*j+1)*PIX] = v1;
            int g = j >> 1;
            s[g] += v0 + v1;
            q[g] += v0*v0 + v1*v1;
        }
    }
#pragma unroll
    for (int g = 0; g < 8; g++) {
        float ss = s[g], qq = q[g];
#pragma unroll
        for (int off = 16; off; off >>= 1) {
            ss += __shfl_xor_sync(0xffffffffu, ss, off);
            qq += __shfl_xor_sync(0xffffffffu, qq, off);
        }
        if ((tid & 31) == 0) { atomicAdd(&sOs[g], ss); atomicAdd(&sOq[g], qq); }
    }
    __syncthreads();
    if (tid < 8) {
        atomicAdd(&g_sout[(b*8 + tid)*2 + 0], sOs[tid]);
        atomicAdd(&g_sout[(b*8 + tid)*2 + 1], sOq[tid]);
    }
}

// ---------------------------------------------- K2b: finalize final GN stats
__global__ void k_stats_out() {
    int t = threadIdx.x;
    if (t < BB*8) {
        float S = g_sout[t*2], Q = g_sout[t*2 + 1];
        float inv = 1.f / (4.f * (float)PIX);
        float mu  = S * inv;
        float var = Q * inv - mu*mu;
        g_mrout[t*2]     = mu;
        g_mrout[t*2 + 1] = rsqrtf(var + 1e-5f);
    }
}

// ------------------------------------------------------ K5: GN + ReLU -> out
__global__ void k_final(float* __restrict__ out,
                        const float* __restrict__ sc,
                        const float* __restrict__ bi) {
    int i4 = blockIdx.x*256 + threadIdx.x;
    int e  = i4 * 4;
    int c = (e >> 16) & 31;
    int b = e >> 21;
    int g = c >> 2;
    float mu = g_mrout[(b*8 + g)*2], rs = g_mrout[(b*8 + g)*2 + 1];
    float scv = sc[c], biv = bi[c];
    float4 v = *(const float4*)(g_pre + e);
    float4 o;
    o.x = fmaxf(fmaf((v.x - mu)*rs, scv, biv), 0.f);
    o.y = fmaxf(fmaf((v.y - mu)*rs, scv, biv), 0.f);
    o.z = fmaxf(fmaf((v.z - mu)*rs, scv, biv), 0.f);
    o.w = fmaxf(fmaf((v.w - mu)*rs, scv, biv), 0.f);
    *(float4*)(out + e) = o;
}

#define SMEM_MAIN ((XCH + WSZ + 16) * (int)sizeof(float))

extern "C" void kernel_launch(void* const* d_in, const int* in_sizes, int n_in,
                              void* d_out, int out_size) {
    const float* x       = (const float*)d_in[0];
    const float* w_off   = (const float*)d_in[1];
    const float* b_off   = (const float*)d_in[2];
    const float* gos     = (const float*)d_in[3];
    const float* gob     = (const float*)d_in[4];
    const float* wdsc    = (const float*)d_in[5];
    const float* bdsc    = (const float*)d_in[6];
    const float* gsc     = (const float*)d_in[7];
    const float* gbi     = (const float*)d_in[8];
    float* out = (float*)d_out;

    cudaFuncSetAttribute(k_main, cudaFuncAttributeMaxDynamicSharedMemorySize, SMEM_MAIN);

    k_zero<<<1, 128>>>();
    k_conv_off<<<dim3(WW/4, BB), 256>>>(x, w_off, b_off);
    k_stats_off<<<1, 32>>>();
    k_py<<<dim3(PIX/256, BB), 256>>>(gos, gob);
    k_main<<<dim3(HH/THM, WW/TWM, BB), 256, SMEM_MAIN>>>(x, wdsc, bdsc);
    k_stats_out<<<1, 32>>>();
    k_final<<<(BB*CC*PIX)/1024, 256>>>(out, gsc, gbi);
}

// round 7
// speedup vs baseline: 1.0134x; 1.0134x over previous
#include <cuda_runtime.h>
#include <cuda_bf16.h>
#include <math.h>

// Problem constants
#define BB 4
#define CC 32
#define WW 256
#define HH 256
#define KK 9
#define OC_OFF 10
#define PIX (WW*HH)

// k_main (mma) tile: 4 w-rows x 32 h-cols = 128 px, 256 threads (8 warps x 16 px)
#define RR 14              // x rows: w0-5 .. w0+8
#define PCW 43             // pair columns: h0-5 .. h0+37
#define PLANE (RR*PCW)     // 602 float2 per channel
#define NCI2 8
#define XDSZ (NCI2*PLANE)  // 4816 float2

typedef unsigned long long u64;
typedef unsigned int u32;

__device__ __forceinline__ u64 ffma2(u64 a, u64 b, u64 c) {
    u64 d;
    asm("fma.rn.f32x2 %0, %1, %2, %3;" : "=l"(d) : "l"(a), "l"(b), "l"(c));
    return d;
}
__device__ __forceinline__ u64 pack2(float v) {
    u64 d; unsigned u = __float_as_uint(v);
    asm("mov.b64 %0, {%1, %1};" : "=l"(d) : "r"(u));
    return d;
}
__device__ __forceinline__ void unpack2(u64 in, float& lo, float& hi) {
    unsigned a, b;
    asm("mov.b64 {%0, %1}, %2;" : "=r"(a), "=r"(b) : "l"(in));
    lo = __uint_as_float(a); hi = __uint_as_float(b);
}
__device__ __forceinline__ u32 tf32r(float v) {
    u32 r;
    asm("cvt.rna.tf32.f32 %0, %1;" : "=r"(r) : "f"(v));
    return r;
}
__device__ __forceinline__ void mma_tf32(float c[4], u32 a0, u32 a1, u32 a2, u32 a3,
                                         u32 b0, u32 b1) {
    asm("mma.sync.aligned.m16n8k8.row.col.f32.tf32.tf32.f32 "
        "{%0,%1,%2,%3}, {%4,%5,%6,%7}, {%8,%9}, {%0,%1,%2,%3};"
        : "+f"(c[0]), "+f"(c[1]), "+f"(c[2]), "+f"(c[3])
        : "r"(a0), "r"(a1), "r"(a2), "r"(a3), "r"(b0), "r"(b1));
}

// Scratch
__device__ float g_off[BB*OC_OFF*PIX];
__device__ float g_py [BB*KK*PIX];
__device__ float g_pre[BB*CC*PIX];
__device__ float g_soff[BB*5*2];
__device__ float g_mroff[BB*5*2];
__device__ float g_sout[BB*8*2];
__device__ float g_mrout[BB*8*2];

// ---------------------------------------------------------------- zero stats
__global__ void k_zero() {
    int t = threadIdx.x;
    if (t < BB*5*2) g_soff[t] = 0.f;
    if (t < BB*8*2) g_sout[t] = 0.f;
}

// ---------------------- K1: 3x3 conv, 32 -> 10 ch, 4 pixels (w-rows) / thread
__global__ void __launch_bounds__(256, 2)
k_conv_off(const float* __restrict__ x,
           const float* __restrict__ w_off,
           const float* __restrict__ b_off) {
    __shared__ __align__(8) float ws[CC*9*OC_OFF];   // [ci][tap][10]
    __shared__ float s_sum[5], s_sq[5];
    int b   = blockIdx.y;
    int wb  = blockIdx.x * 4;
    int tid = threadIdx.x;
    int h   = tid;

    for (int i = tid; i < CC*9*OC_OFF; i += 256) {
        int o = i % OC_OFF; int rest = i / OC_OFF;
        int tap = rest % 9; int ci = rest / 9;
        int dy = tap / 3, dx = tap % 3;
        ws[i] = w_off[((o*CC + ci)*3 + dy)*3 + dx];
    }
    if (tid < 5) { s_sum[tid] = 0.f; s_sq[tid] = 0.f; }
    __syncthreads();

    u64 acc[4][5];
    const u64* b2 = (const u64*)b_off;
#pragma unroll
    for (int p = 0; p < 4; p++)
#pragma unroll
        for (int j = 0; j < 5; j++) acc[p][j] = b2[j];

    const float* xb = x + b*CC*PIX;
#pragma unroll 1
    for (int ci = 0; ci < CC; ci++) {
        const float* xc = xb + ci*PIX;
        u64 v2[6][3];
#pragma unroll
        for (int rr = 0; rr < 6; rr++) {
            int r = wb - 1 + rr;
            bool rok = (unsigned)r < 256u;
#pragma unroll
            for (int dx = 0; dx < 3; dx++) {
                int c = h + dx - 1;
                float v = (rok && (unsigned)c < 256u) ? xc[r*256 + c] : 0.f;
                v2[rr][dx] = pack2(v);
            }
        }
#pragma unroll
        for (int tap = 0; tap < 9; tap++) {
            int dy = tap / 3, dx = tap % 3;
            const u64* wp = (const u64*)&ws[(ci*9 + tap)*OC_OFF];
            u64 w0 = wp[0], w1 = wp[1], w2 = wp[2], w3 = wp[3], w4 = wp[4];
#pragma unroll
            for (int p = 0; p < 4; p++) {
                u64 vv = v2[dy + p][dx];
                acc[p][0] = ffma2(vv, w0, acc[p][0]);
                acc[p][1] = ffma2(vv, w1, acc[p][1]);
                acc[p][2] = ffma2(vv, w2, acc[p][2]);
                acc[p][3] = ffma2(vv, w3, acc[p][3]);
                acc[p][4] = ffma2(vv, w4, acc[p][4]);
            }
        }
    }

    float s[5], q[5];
#pragma unroll
    for (int j = 0; j < 5; j++) { s[j] = 0.f; q[j] = 0.f; }
#pragma unroll
    for (int p = 0; p < 4; p++) {
        int w = wb + p;
        float* outp = g_off + b*OC_OFF*PIX + w*256 + h;
#pragma unroll
        for (int j = 0; j < 5; j++) {
            float v0, v1; unpack2(acc[p][j], v0, v1);
            outp[(2*j)*PIX]   = v0;
            outp[(2*j+1)*PIX] = v1;
            s[j] += v0 + v1;
            q[j] += v0*v0 + v1*v1;
        }
    }
#pragma unroll
    for (int j = 0; j < 5; j++) {
        float ss = s[j], qq = q[j];
#pragma unroll
        for (int off = 16; off; off >>= 1) {
            ss += __shfl_xor_sync(0xffffffffu, ss, off);
            qq += __shfl_xor_sync(0xffffffffu, qq, off);
        }
        if ((tid & 31) == 0) { atomicAdd(&s_sum[j], ss); atomicAdd(&s_sq[j], qq); }
    }
    __syncthreads();
    if (tid < 5) {
        atomicAdd(&g_soff[(b*5 + tid)*2 + 0], s_sum[tid]);
        atomicAdd(&g_soff[(b*5 + tid)*2 + 1], s_sq[tid]);
    }
}

// --------------------------------------------- K2a: finalize offset GN stats
__global__ void k_stats_off() {
    int t = threadIdx.x;
    if (t < BB*5) {
        float S = g_soff[t*2], Q = g_soff[t*2 + 1];
        float inv = 1.f / (2.f * (float)PIX);
        float mu  = S * inv;
        float var = Q * inv - mu*mu;
        g_mroff[t*2]     = mu;
        g_mroff[t*2 + 1] = rsqrtf(var + 1e-5f);
    }
}

// --------------------- K3: GN + tanh + cumsum -> sampling coordinate field py
__global__ void k_py(const float* __restrict__ sc, const float* __restrict__ bi) {
    int b = blockIdx.y;
    int p = blockIdx.x*256 + threadIdx.x;
    int w = p >> 8;

    float t[9];
#pragma unroll
    for (int c = 0; c < 9; c++) {
        float v  = g_off[(b*OC_OFF + c)*PIX + p];
        int   g  = c >> 1;
        float mu = g_mroff[(b*5 + g)*2], rs = g_mroff[(b*5 + g)*2 + 1];
        t[c] = tanhf(fmaf((v - mu)*rs, sc[c], bi[c]));
    }
    float yc[9];
    float r0 = t[3];
    float r1 = r0 + t[2];
    float r2 = r1 + t[1];
    float r3 = r2 + t[0];
    yc[0] = r3; yc[1] = r2; yc[2] = r1; yc[3] = r0;
    yc[4] = 0.f;
    float u0 = t[5];
    float u1 = u0 + t[6];
    float u2 = u1 + t[7];
    float u3 = u2 + t[8];
    yc[5] = u0; yc[6] = u1; yc[7] = u2; yc[8] = u3;

#pragma unroll
    for (int k = 0; k < 9; k++) {
        float y  = (float)w + yc[k];
        float tt = fminf(fmaxf(y * (1.f/256.f), 0.f), 1.f);
        g_py[(b*KK + k)*PIX + p] = tt * 255.f;
    }
}

// -------- K4: fused bilinear-sample + (K,1)-strided conv via tf32 mma.sync
// Smem layout (bytes):
//   geoW  float4[1152]   @ 0        (18432)
//   XsD   float2[4816]   @ 18432    (38528)
//   Bp    uint2 [4608]   @ 56960    (36864)
//   geoO  int2  [1152]   @ 93824    ( 9216)
//   stats float [16]     @ 103040   (   64)
#define SM_GEOW 0
#define SM_XSD  18432
#define SM_BP   56960
#define SM_GEOO 93824
#define SM_STAT 103040
#define SMEM_MAIN (103104 + 64)

__global__ void __launch_bounds__(256, 2)
k_main(const float* __restrict__ x,
       const float* __restrict__ wdsc,
       const float* __restrict__ bdsc) {
    extern __shared__ __align__(16) char smraw[];
    float4* geoW = (float4*)(smraw + SM_GEOW);
    float2* XsD  = (float2*)(smraw + SM_XSD);
    uint2*  Bp   = (uint2*) (smraw + SM_BP);
    int2*   geoO = (int2*)  (smraw + SM_GEOO);
    float*  sOs  = (float*) (smraw + SM_STAT);
    float*  sOq  = sOs + 8;

    int b  = blockIdx.z;
    int w0 = blockIdx.y * 4;
    int h0 = blockIdx.x * 32;
    int tid = threadIdx.x;
    int warp = tid >> 5;
    int T = tid & 31;
    int rbase = w0 - 5, cbase = h0 - 5;

    // --- pack B fragments (tf32-rounded, per-lane layout) ---
    for (int i = tid; i < 4*9*4*32; i += 256) {
        int lane = i & 31; int rest = i >> 5;
        int nb = rest & 3; rest >>= 2;
        int kk = rest % 9; int q = rest / 9;
        int c8 = lane & 3, co = nb*8 + (lane >> 2);
        float wv0 = wdsc[(co*CC + q*8 + c8)*KK + kk];
        float wv1 = wdsc[(co*CC + q*8 + c8 + 4)*KK + kk];
        Bp[i] = make_uint2(tf32r(wv0), tf32r(wv1));
    }
    // --- geometry table: per (local px, kk) ---
    for (int i = tid; i < 128*9; i += 256) {
        int kk = i % 9; int p = i / 9;
        int w = w0 + (p >> 5), h = h0 + (p & 31);
        float py = g_py[(b*KK + kk)*PIX + w*256 + h];
        float y0f = floorf(py);
        float wy  = py - y0f;
        int y0 = (int)y0f;
        int y1 = min(y0 + 1, 255);
        int rs0 = y0 - rbase, rs1 = y1 - rbase;
        float fx = (float)(h + kk - 4);
        float pxv = fminf(fmaxf(fx * (1.f/256.f), 0.f), 1.f) * 255.f;
        float x0f = floorf(pxv);
        float wx  = pxv - x0f;
        int cs0 = (int)x0f - cbase;
        geoW[i] = make_float4((1.f-wy)*(1.f-wx), (1.f-wy)*wx, wy*(1.f-wx), wy*wx);
        geoO[i] = make_int2(rs0*PCW + cs0, rs1*PCW + cs0);
    }
    if (tid < 8) { sOs[tid] = 0.f; sOq[tid] = 0.f; }

    float c[4][4];
#pragma unroll
    for (int nb = 0; nb < 4; nb++)
#pragma unroll
        for (int j = 0; j < 4; j++) c[nb][j] = 0.f;

    int p0 = (warp << 4) + (T >> 2);
    int p1 = p0 + 8;
    const float2* Pl0 = XsD + (T & 3)*PLANE;
    const float2* Pl1 = XsD + ((T & 3) + 4)*PLANE;

#pragma unroll 1
    for (int q = 0; q < 4; q++) {
        __syncthreads();
        // stage 8-channel pair tile
        const float* xq = x + (b*CC + q*NCI2)*PIX;
        for (int i = tid; i < XDSZ; i += 256) {
            int cc = i % PCW; int rest = i / PCW;
            int r = rest % RR; int ci8 = rest / RR;
            int gr  = min(max(rbase + r, 0), 255);
            int gc0 = min(max(cbase + cc, 0), 255);
            int gc1 = min(max(cbase + cc + 1, 0), 255);
            const float* xp = xq + ci8*PIX + gr*256;
            XsD[i] = make_float2(xp[gc0], xp[gc1]);
        }
        __syncthreads();

#pragma unroll 1
        for (int kk = 0; kk < 9; kk++) {
            float4 gw0 = geoW[p0*9 + kk]; int2 go0 = geoO[p0*9 + kk];
            float4 gw1 = geoW[p1*9 + kk]; int2 go1 = geoO[p1*9 + kk];

            float2 A00 = Pl0[go0.x], A01 = Pl0[go0.y];
            float v0 = gw0.x*A00.x;
            v0 = fmaf(gw0.y, A00.y, v0);
            v0 = fmaf(gw0.z, A01.x, v0);
            v0 = fmaf(gw0.w, A01.y, v0);
            float2 A10 = Pl0[go1.x], A11 = Pl0[go1.y];
            float v1 = gw1.x*A10.x;
            v1 = fmaf(gw1.y, A10.y, v1);
            v1 = fmaf(gw1.z, A11.x, v1);
            v1 = fmaf(gw1.w, A11.y, v1);
            float2 A20 = Pl1[go0.x], A21 = Pl1[go0.y];
            float v2 = gw0.x*A20.x;
            v2 = fmaf(gw0.y, A20.y, v2);
            v2 = fmaf(gw0.z, A21.x, v2);
            v2 = fmaf(gw0.w, A21.y, v2);
            float2 A30 = Pl1[go1.x], A31 = Pl1[go1.y];
            float v3 = gw1.x*A30.x;
            v3 = fmaf(gw1.y, A30.y, v3);
            v3 = fmaf(gw1.z, A31.x, v3);
            v3 = fmaf(gw1.w, A31.y, v3);

            u32 a0 = tf32r(v0), a1 = tf32r(v1), a2 = tf32r(v2), a3 = tf32r(v3);

            const uint2* bp = Bp + ((q*9 + kk)*4)*32 + T;
#pragma unroll
            for (int nb = 0; nb < 4; nb++) {
                uint2 bb = bp[nb*32];
                mma_tf32(c[nb], a0, a1, a2, a3, bb.x, bb.y);
            }
        }
    }

    // --- epilogue: bias, store pre-GN, GN stats ---
    int m = T & 3;
    int h_a = h0 + (p0 & 31), w_a = w0 + (p0 >> 5);
    int h_b = h0 + (p1 & 31);
    float* preb = g_pre + (b*CC)*PIX + w_a*256;

    float s[8], qsum[8];
#pragma unroll
    for (int g = 0; g < 8; g++) { s[g] = 0.f; qsum[g] = 0.f; }
#pragma unroll
    for (int nb = 0; nb < 4; nb++) {
        int co0 = nb*8 + 2*m, co1 = co0 + 1;
        float bv0 = __ldg(&bdsc[co0]), bv1 = __ldg(&bdsc[co1]);
        float v00 = c[nb][0] + bv0;
        float v01 = c[nb][1] + bv1;
        float v10 = c[nb][2] + bv0;
        float v11 = c[nb][3] + bv1;
        preb[co0*PIX + h_a] = v00;
        preb[co1*PIX + h_a] = v01;
        preb[co0*PIX + h_b] = v10;
        preb[co1*PIX + h_b] = v11;
        int g = co0 >> 2;
        s[g]    += v00 + v01 + v10 + v11;
        qsum[g] += v00*v00 + v01*v01 + v10*v10 + v11*v11;
    }
#pragma unroll
    for (int g = 0; g < 8; g++) {
        float ss = s[g], qq = qsum[g];
#pragma unroll
        for (int off = 16; off; off >>= 1) {
            ss += __shfl_xor_sync(0xffffffffu, ss, off);
            qq += __shfl_xor_sync(0xffffffffu, qq, off);
        }
        if (T == 0) { atomicAdd(&sOs[g], ss); atomicAdd(&sOq[g], qq); }
    }
    __syncthreads();
    if (tid < 8) {
        atomicAdd(&g_sout[(b*8 + tid)*2 + 0], sOs[tid]);
        atomicAdd(&g_sout[(b*8 + tid)*2 + 1], sOq[tid]);
    }
}

// ---------------------------------------------- K2b: finalize final GN stats
__global__ void k_stats_out() {
    int t = threadIdx.x;
    if (t < BB*8) {
        float S = g_sout[t*2], Q = g_sout[t*2 + 1];
        float inv = 1.f / (4.f * (float)PIX);
        float mu  = S * inv;
        float var = Q * inv - mu*mu;
        g_mrout[t*2]     = mu;
        g_mrout[t*2 + 1] = rsqrtf(var + 1e-5f);
    }
}

// ------------------------------------------------------ K5: GN + ReLU -> out
__global__ void k_final(float* __restrict__ out,
                        const float* __restrict__ sc,
                        const float* __restrict__ bi) {
    int i4 = blockIdx.x*256 + threadIdx.x;
    int e  = i4 * 4;
    int c = (e >> 16) & 31;
    int b = e >> 21;
    int g = c >> 2;
    float mu = g_mrout[(b*8 + g)*2], rs = g_mrout[(b*8 + g)*2 + 1];
    float scv = sc[c], biv = bi[c];
    float4 v = *(const float4*)(g_pre + e);
    float4 o;
    o.x = fmaxf(fmaf((v.x - mu)*rs, scv, biv), 0.f);
    o.y = fmaxf(fmaf((v.y - mu)*rs, scv, biv), 0.f);
    o.z = fmaxf(fmaf((v.z - mu)*rs, scv, biv), 0.f);
    o.w = fmaxf(fmaf((v.w - mu)*rs, scv, biv), 0.f);
    *(float4*)(out + e) = o;
}

extern "C" void kernel_launch(void* const* d_in, const int* in_sizes, int n_in,
                              void* d_out, int out_size) {
    const float* x       = (const float*)d_in[0];
    const float* w_off   = (const float*)d_in[1];
    const float* b_off   = (const float*)d_in[2];
    const float* gos     = (const float*)d_in[3];
    const float* gob     = (const float*)d_in[4];
    const float* wdsc    = (const float*)d_in[5];
    const float* bdsc    = (const float*)d_in[6];
    const float* gsc     = (const float*)d_in[7];
    const float* gbi     = (const float*)d_in[8];
    float* out = (float*)d_out;

    cudaFuncSetAttribute(k_main, cudaFuncAttributeMaxDynamicSharedMemorySize, SMEM_MAIN);

    k_zero<<<1, 128>>>();
    k_conv_off<<<dim3(WW/4, BB), 256>>>(x, w_off, b_off);
    k_stats_off<<<1, 32>>>();
    k_py<<<dim3(PIX/256, BB), 256>>>(gos, gob);
    k_main<<<dim3(HH/32, WW/4, BB), 256, SMEM_MAIN>>>(x, wdsc, bdsc);
    k_stats_out<<<1, 32>>>();
    k_final<<<(BB*CC*PIX)/1024, 256>>>(out, gsc, gbi);
}